// round 1
// baseline (speedup 1.0000x reference)
#include <cuda_runtime.h>
#include <cuda_bf16.h>
#include <cstdint>

// Problem dims
#define Ldim 2
#define Bdim 8
#define Tdim 256
#define Ndim 512
#define Kdim 16
#define Mdim 10000
#define Hdim 256
#define Rdim 500

// Scratch (device globals -- no allocation allowed)
__device__ float g_u0[Bdim * Ndim * Hdim];       // 4 MB
__device__ float g_q[Bdim * Tdim * Hdim];        // 2 MB
__device__ float g_k[Bdim * Ndim * Hdim];        // 4 MB
__device__ float g_wd[Bdim * Tdim * Hdim];       // 2 MB
__device__ float g_ug[Bdim * Tdim * Hdim];       // 2 MB
__device__ float g_pasi[Bdim * Tdim * Ndim];     // 4 MB
__device__ float g_a[Bdim];

__device__ __forceinline__ float warp_sum(float v) {
    #pragma unroll
    for (int o = 16; o > 0; o >>= 1) v += __shfl_xor_sync(0xffffffffu, v, o);
    return v;
}
__device__ __forceinline__ float warp_max(float v) {
    #pragma unroll
    for (int o = 16; o > 0; o >>= 1) v = fmaxf(v, __shfl_xor_sync(0xffffffffu, v, o));
    return v;
}

// ---------------------------------------------------------------------------
// Kernel 1: u0 = concat([sum_k SE[heads], sum_k SE[tails]]) @ squeeze_w.T + b,
//           zeroed where tri_mask != 1.
// grid: (B*N/16) blocks of 256 threads. Each block: 16 (b,n) rows.
// ---------------------------------------------------------------------------
__global__ __launch_bounds__(256) void u0_kernel(
    const float* __restrict__ SE,          // (B,M,H)
    const int*   __restrict__ heads,       // (B,N,K)
    const int*   __restrict__ tails,       // (B,N,K)
    const float* __restrict__ squeeze_w,   // (H,2H)
    const float* __restrict__ squeeze_b,   // (H)
    const int*   __restrict__ tri_mask)    // (B,N)
{
    __shared__ float cat_s[16][512];       // 32 KB
    __shared__ int   sidx[16][32];         // heads 0..15, tails 16..31

    const int tid  = threadIdx.x;
    const int row0 = blockIdx.x * 16;      // flattened b*N+n
    const int b    = row0 / Ndim;

    for (int i = tid; i < 16 * 32; i += 256) {
        int r = i >> 5, j = i & 31;
        int gr = row0 + r;
        sidx[r][j] = (j < 16) ? heads[gr * Kdim + j] : tails[gr * Kdim + (j - 16)];
    }
    __syncthreads();

    const float* SEb = SE + (size_t)b * Mdim * Hdim;
    for (int r = 0; r < 16; r++) {
        float he = 0.f, te = 0.f;
        #pragma unroll
        for (int k = 0; k < 16; k++) {
            he += SEb[(size_t)sidx[r][k] * Hdim + tid];
            te += SEb[(size_t)sidx[r][16 + k] * Hdim + tid];
        }
        cat_s[r][tid]       = he;
        cat_s[r][256 + tid] = te;
    }
    __syncthreads();

    // GEMM: out[r][tid] = sum_j cat_s[r][j] * squeeze_w[tid*512 + j]
    float acc[16];
    #pragma unroll
    for (int r = 0; r < 16; r++) acc[r] = 0.f;

    const float4* W4 = (const float4*)(squeeze_w + (size_t)tid * 512);
    for (int j4 = 0; j4 < 128; j4++) {
        float4 w = W4[j4];
        #pragma unroll
        for (int r = 0; r < 16; r++) {
            float4 c = *(const float4*)&cat_s[r][j4 * 4];
            acc[r] += c.x * w.x + c.y * w.y + c.z * w.z + c.w * w.w;
        }
    }
    float bias = squeeze_b[tid];
    for (int r = 0; r < 16; r++) {
        int gr = row0 + r;
        float v = (tri_mask[gr] == 1) ? (acc[r] + bias) : 0.f;
        g_u0[(size_t)gr * Hdim + tid] = v;
    }
}

// ---------------------------------------------------------------------------
// Kernel 2: q, wd, ug from h_last via three GEMMs sharing the X tile.
// grid: (B*T/8) blocks of 256 threads.
// ---------------------------------------------------------------------------
__global__ __launch_bounds__(256) void qdg_kernel(
    const float* __restrict__ hlast,       // (B*T, H)
    const float* __restrict__ wq, const float* __restrict__ bq,
    const float* __restrict__ wd, const float* __restrict__ bd,
    const float* __restrict__ wg, const float* __restrict__ bg)
{
    __shared__ float xs[8][256];           // 8 KB
    const int tid  = threadIdx.x;
    const int row0 = blockIdx.x * 8;

    for (int r = 0; r < 8; r++) xs[r][tid] = hlast[(size_t)(row0 + r) * Hdim + tid];
    __syncthreads();

    float aq[8], ad[8], ag[8];
    #pragma unroll
    for (int r = 0; r < 8; r++) { aq[r] = 0.f; ad[r] = 0.f; ag[r] = 0.f; }

    const float4* Q4 = (const float4*)(wq + (size_t)tid * Hdim);
    const float4* D4 = (const float4*)(wd + (size_t)tid * Hdim);
    const float4* G4 = (const float4*)(wg + (size_t)tid * Hdim);
    for (int j4 = 0; j4 < 64; j4++) {
        float4 q4 = Q4[j4], d4 = D4[j4], g4 = G4[j4];
        #pragma unroll
        for (int r = 0; r < 8; r++) {
            float4 x = *(const float4*)&xs[r][j4 * 4];
            aq[r] += x.x * q4.x + x.y * q4.y + x.z * q4.z + x.w * q4.w;
            ad[r] += x.x * d4.x + x.y * d4.y + x.z * d4.z + x.w * d4.w;
            ag[r] += x.x * g4.x + x.y * g4.y + x.z * g4.z + x.w * g4.w;
        }
    }
    float bqv = bq[tid], bdv = bd[tid], bgv = bg[tid];
    for (int r = 0; r < 8; r++) {
        size_t o = (size_t)(row0 + r) * Hdim + tid;
        g_q[o]  = (aq[r] + bqv) * 0.0625f;   // * H^-0.5
        g_wd[o] = ad[r] + bdv;
        g_ug[o] = ag[r] + bgv;
    }
}

// ---------------------------------------------------------------------------
// Kernel 3: k = rel_table[relations_idx] @ wk.T + bk
// grid: (B*N/16) blocks of 256 threads.
// ---------------------------------------------------------------------------
__global__ __launch_bounds__(256) void k_kernel(
    const float* __restrict__ rel_table,   // (R,H)
    const int*   __restrict__ ridx_g,      // (B,N)
    const float* __restrict__ wk, const float* __restrict__ bk)
{
    __shared__ float xs[16][256];          // 16 KB
    __shared__ int   ridx[16];
    const int tid  = threadIdx.x;
    const int row0 = blockIdx.x * 16;

    if (tid < 16) ridx[tid] = ridx_g[row0 + tid];
    __syncthreads();
    for (int i = tid; i < 16 * 256; i += 256) {
        int r = i >> 8, j = i & 255;
        xs[r][j] = rel_table[(size_t)ridx[r] * Hdim + j];
    }
    __syncthreads();

    float acc[16];
    #pragma unroll
    for (int r = 0; r < 16; r++) acc[r] = 0.f;
    const float4* W4 = (const float4*)(wk + (size_t)tid * Hdim);
    for (int j4 = 0; j4 < 64; j4++) {
        float4 w = W4[j4];
        #pragma unroll
        for (int r = 0; r < 16; r++) {
            float4 x = *(const float4*)&xs[r][j4 * 4];
            acc[r] += x.x * w.x + x.y * w.y + x.z * w.z + x.w * w.w;
        }
    }
    float bkv = bk[tid];
    for (int r = 0; r < 16; r++)
        g_k[(size_t)(row0 + r) * Hdim + tid] = acc[r] + bkv;
}

// ---------------------------------------------------------------------------
// Kernel 4: scores = q.k^T (masked) then softmax over n -> pasi
// grid: (B*T/8) blocks of 256 threads. Each block: 8 t-rows of one batch.
// ---------------------------------------------------------------------------
__global__ __launch_bounds__(256) void score_kernel(const int* __restrict__ tri_mask)
{
    __shared__ float qs[8][256];           // 8 KB
    __shared__ float sc[8][512];           // 16 KB
    const int tid  = threadIdx.x;
    const int row0 = blockIdx.x * 8;       // flattened b*T + t
    const int b    = row0 / Tdim;

    for (int r = 0; r < 8; r++) qs[r][tid] = g_q[(size_t)(row0 + r) * Hdim + tid];
    __syncthreads();

    float a0[8], a1[8];
    #pragma unroll
    for (int r = 0; r < 8; r++) { a0[r] = 0.f; a1[r] = 0.f; }

    const float* kb = g_k + (size_t)b * Ndim * Hdim;
    const float4* K0 = (const float4*)(kb + (size_t)tid * Hdim);
    const float4* K1 = (const float4*)(kb + (size_t)(tid + 256) * Hdim);
    for (int j4 = 0; j4 < 64; j4++) {
        float4 k0 = K0[j4], k1 = K1[j4];
        #pragma unroll
        for (int r = 0; r < 8; r++) {
            float4 q = *(const float4*)&qs[r][j4 * 4];
            a0[r] += q.x * k0.x + q.y * k0.y + q.z * k0.z + q.w * k0.w;
            a1[r] += q.x * k1.x + q.y * k1.y + q.z * k1.z + q.w * k1.w;
        }
    }
    int m0 = tri_mask[b * Ndim + tid];
    int m1 = tri_mask[b * Ndim + tid + 256];
    for (int r = 0; r < 8; r++) {
        sc[r][tid]       = (m0 == 1) ? a0[r] : -1.0e9f;
        sc[r][tid + 256] = (m1 == 1) ? a1[r] : -1.0e9f;
    }
    __syncthreads();

    // softmax: warp w handles row w
    const int wid = tid >> 5, lane = tid & 31;
    float* row = sc[wid];
    float mx = -3.4e38f;
    #pragma unroll
    for (int i = lane; i < 512; i += 32) mx = fmaxf(mx, row[i]);
    mx = warp_max(mx);
    float sum = 0.f;
    #pragma unroll
    for (int i = lane; i < 512; i += 32) {
        float e = __expf(row[i] - mx);
        row[i] = e;
        sum += e;
    }
    sum = warp_sum(sum);
    float inv = __fdividef(1.0f, sum);
    float* pout = g_pasi + (size_t)(row0 + wid) * Ndim;
    #pragma unroll
    for (int i = lane; i < 512; i += 32) pout[i] = row[i] * inv;
}

// ---------------------------------------------------------------------------
// Kernel 5: aerfa_last[b] = sigmoid(h_last[b,T-1,:] . aerfa_w + aerfa_b)
// ---------------------------------------------------------------------------
__global__ __launch_bounds__(256) void aerfa_kernel(
    const float* __restrict__ hlast,
    const float* __restrict__ aw, const float* __restrict__ ab)
{
    const int b = threadIdx.x >> 5, lane = threadIdx.x & 31;
    const float* x = hlast + ((size_t)b * Tdim + (Tdim - 1)) * Hdim;
    float s = 0.f;
    #pragma unroll
    for (int j = lane; j < Hdim; j += 32) s += x[j] * aw[j];
    s = warp_sum(s);
    if (lane == 0) g_a[b] = __fdividef(1.0f, 1.0f + __expf(-(s + ab[0])));
}

// ---------------------------------------------------------------------------
// Kernel 6: the sequential scan. One warp per (b,n), u in registers.
// grid: (N/8, B) blocks of 256 threads (8 warps).
// h mapping: lane holds h = lane*8 + j  (contiguous -> float4 loads coalesce)
// ---------------------------------------------------------------------------
__global__ __launch_bounds__(256) void scan_kernel(
    const float* __restrict__ wu_w,        // (1,H)
    const float* __restrict__ wu_b,        // (1)
    float* __restrict__ out)               // (B,T,H)
{
    __shared__ float sacc[8 * 256];        // 8 KB
    const int b    = blockIdx.y;
    const int wid  = threadIdx.x >> 5;
    const int lane = threadIdx.x & 31;
    const int n    = blockIdx.x * 8 + wid;
    const int tid  = threadIdx.x;

    float u[8], wv[8];
    {
        const float4* u0p = (const float4*)(g_u0 + ((size_t)b * Ndim + n) * Hdim + lane * 8);
        float4 ua = u0p[0], ub = u0p[1];
        u[0]=ua.x; u[1]=ua.y; u[2]=ua.z; u[3]=ua.w;
        u[4]=ub.x; u[5]=ub.y; u[6]=ub.z; u[7]=ub.w;
        const float4* wp = (const float4*)(wu_w + lane * 8);
        float4 wa = wp[0], wb = wp[1];
        wv[0]=wa.x; wv[1]=wa.y; wv[2]=wa.z; wv[3]=wa.w;
        wv[4]=wb.x; wv[5]=wb.y; wv[6]=wb.z; wv[7]=wb.w;
    }
    const float wub = wu_b[0];
    const float ab  = g_a[b];
    const float* pas = g_pasi + (size_t)b * Tdim * Ndim + n;
    const float* wdb = g_wd + (size_t)b * Tdim * Hdim + lane * 8;
    const float* ugb = g_ug + (size_t)b * Tdim * Hdim + lane * 8;
    float* outb = out + (size_t)b * Tdim * Hdim;

    for (int t = 0; t < Tdim; t++) {
        float4 wda = *(const float4*)(wdb + (size_t)t * Hdim);
        float4 wdc = *(const float4*)(wdb + (size_t)t * Hdim + 4);
        float4 uga = *(const float4*)(ugb + (size_t)t * Hdim);
        float4 ugc = *(const float4*)(ugb + (size_t)t * Hdim + 4);
        float wd_[8] = {wda.x, wda.y, wda.z, wda.w, wdc.x, wdc.y, wdc.z, wdc.w};
        float ug_[8] = {uga.x, uga.y, uga.z, uga.w, ugc.x, ugc.y, ugc.z, ugc.w};

        // wu = u . wu_w + wu_b  (warp reduce)
        float s = 0.f;
        #pragma unroll
        for (int j = 0; j < 8; j++) s += u[j] * wv[j];
        s = warp_sum(s);
        float wu = s + wub;

        float p = pas[(size_t)t * Ndim];

        #pragma unroll
        for (int j = 0; j < 8; j++) {
            // beta = sigmoid(wd + wu) * a  =  a / (1 + exp(-(wd+wu)))
            float beta = __fdividef(ab, 1.0f + __expf(-(wd_[j] + wu)));
            u[j] = fmaf(beta, ug_[j] - u[j], u[j]);   // u*(1-b) + ug*b
            sacc[wid * 256 + lane * 8 + j] = u[j] * p;
        }
        __syncthreads();
        {
            float sum = 0.f;
            #pragma unroll
            for (int w = 0; w < 8; w++) sum += sacc[w * 256 + tid];
            atomicAdd(&outb[(size_t)t * Hdim + tid], sum);
        }
        __syncthreads();
    }
}

// ---------------------------------------------------------------------------
extern "C" void kernel_launch(void* const* d_in, const int* in_sizes, int n_in,
                              void* d_out, int out_size)
{
    const float* hidden   = (const float*)d_in[0];
    const float* SE       = (const float*)d_in[1];
    const float* rel_tab  = (const float*)d_in[2];
    const float* sq_w     = (const float*)d_in[3];
    const float* sq_b     = (const float*)d_in[4];
    const float* ae_w     = (const float*)d_in[5];
    const float* ae_b     = (const float*)d_in[6];
    const float* wq_w     = (const float*)d_in[7];
    const float* wq_b     = (const float*)d_in[8];
    const float* wk_w     = (const float*)d_in[9];
    const float* wk_b     = (const float*)d_in[10];
    const float* wd_w     = (const float*)d_in[11];
    const float* wd_b     = (const float*)d_in[12];
    const float* wu_w     = (const float*)d_in[13];
    const float* wu_b     = (const float*)d_in[14];
    const float* wg_w     = (const float*)d_in[15];
    const float* wg_b     = (const float*)d_in[16];
    const int*   heads    = (const int*)d_in[17];
    const int*   tails    = (const int*)d_in[18];
    const int*   tri_mask = (const int*)d_in[19];
    const int*   rel_idx  = (const int*)d_in[20];
    float* out = (float*)d_out;

    const float* h_last = hidden + (size_t)(Ldim - 1) * Bdim * Tdim * Hdim;

    cudaMemsetAsync(out, 0, (size_t)out_size * sizeof(float), 0);

    u0_kernel<<<(Bdim * Ndim) / 16, 256>>>(SE, heads, tails, sq_w, sq_b, tri_mask);
    qdg_kernel<<<(Bdim * Tdim) / 8, 256>>>(h_last, wq_w, wq_b, wd_w, wd_b, wg_w, wg_b);
    k_kernel<<<(Bdim * Ndim) / 16, 256>>>(rel_tab, rel_idx, wk_w, wk_b);
    aerfa_kernel<<<1, 256>>>(h_last, ae_w, ae_b);
    score_kernel<<<(Bdim * Tdim) / 8, 256>>>(tri_mask);
    scan_kernel<<<dim3(Ndim / 8, Bdim), 256>>>(wu_w, wu_b, out);
}

// round 4
// speedup vs baseline: 1.0347x; 1.0347x over previous
#include <cuda_runtime.h>
#include <cuda_bf16.h>
#include <cstdint>

// Problem dims
#define Ldim 2
#define Bdim 8
#define Tdim 256
#define Ndim 512
#define Kdim 16
#define Mdim 10000
#define Hdim 256
#define Rdim 500

// Scratch (device globals -- no allocation allowed)
__device__ float g_u0[Bdim * Ndim * Hdim];       // 4 MB
__device__ float g_q[Bdim * Tdim * Hdim];        // 2 MB
__device__ float g_k[Bdim * Ndim * Hdim];        // 4 MB
__device__ float g_ewd[Bdim * Tdim * Hdim];      // 2 MB : exp(-(h@wd.T+bd))
__device__ float g_ug[Bdim * Tdim * Hdim];       // 2 MB
__device__ float g_pasi[Bdim * Tdim * Ndim];     // 4 MB
__device__ float g_a[Bdim];

__device__ __forceinline__ float warp_sum(float v) {
    #pragma unroll
    for (int o = 16; o > 0; o >>= 1) v += __shfl_xor_sync(0xffffffffu, v, o);
    return v;
}
__device__ __forceinline__ float warp_max(float v) {
    #pragma unroll
    for (int o = 16; o > 0; o >>= 1) v = fmaxf(v, __shfl_xor_sync(0xffffffffu, v, o));
    return v;
}

// ---------------------------------------------------------------------------
// Kernel 1: u0 = concat([sum_k SE[heads], sum_k SE[tails]]) @ squeeze_w.T + b,
//           zeroed where tri_mask != 1.  grid: 256 blocks x 256 thr (16 rows).
// ---------------------------------------------------------------------------
__global__ __launch_bounds__(256) void u0_kernel(
    const float* __restrict__ SE,          // (B,M,H)
    const int*   __restrict__ heads,       // (B,N,K)
    const int*   __restrict__ tails,       // (B,N,K)
    const float* __restrict__ squeeze_w,   // (H,2H)
    const float* __restrict__ squeeze_b,   // (H)
    const int*   __restrict__ tri_mask)    // (B,N)
{
    __shared__ float cat_s[16][512];       // 32 KB
    __shared__ int   sidx[16][32];         // heads 0..15, tails 16..31

    const int tid  = threadIdx.x;
    const int row0 = blockIdx.x * 16;      // flattened b*N+n
    const int b    = row0 / Ndim;

    for (int i = tid; i < 16 * 32; i += 256) {
        int r = i >> 5, j = i & 31;
        int gr = row0 + r;
        sidx[r][j] = (j < 16) ? heads[gr * Kdim + j] : tails[gr * Kdim + (j - 16)];
    }
    __syncthreads();

    const float* SEb = SE + (size_t)b * Mdim * Hdim;
    for (int r = 0; r < 16; r++) {
        float he = 0.f, te = 0.f;
        #pragma unroll
        for (int k = 0; k < 16; k++) {
            he += SEb[(size_t)sidx[r][k] * Hdim + tid];
            te += SEb[(size_t)sidx[r][16 + k] * Hdim + tid];
        }
        cat_s[r][tid]       = he;
        cat_s[r][256 + tid] = te;
    }
    __syncthreads();

    float acc[16];
    #pragma unroll
    for (int r = 0; r < 16; r++) acc[r] = 0.f;

    const float4* W4 = (const float4*)(squeeze_w + (size_t)tid * 512);
    for (int j4 = 0; j4 < 128; j4++) {
        float4 w = W4[j4];
        #pragma unroll
        for (int r = 0; r < 16; r++) {
            float4 c = *(const float4*)&cat_s[r][j4 * 4];
            acc[r] += c.x * w.x + c.y * w.y + c.z * w.z + c.w * w.w;
        }
    }
    float bias = squeeze_b[tid];
    for (int r = 0; r < 16; r++) {
        int gr = row0 + r;
        float v = (tri_mask[gr] == 1) ? (acc[r] + bias) : 0.f;
        g_u0[(size_t)gr * Hdim + tid] = v;
    }
}

// ---------------------------------------------------------------------------
// Kernel 2 (fused): blocks [0,256)  : q, ewd=exp(-wd), ug from h_last
//                   blocks [256,512): k = rel_table[ridx] @ wk.T + bk
//                   block  512      : aerfa per batch
// ---------------------------------------------------------------------------
__global__ __launch_bounds__(256) void mid_kernel(
    const float* __restrict__ hlast,       // (B*T, H)
    const float* __restrict__ wq, const float* __restrict__ bq,
    const float* __restrict__ wd, const float* __restrict__ bd,
    const float* __restrict__ wg, const float* __restrict__ bg,
    const float* __restrict__ rel_table,   // (R,H)
    const int*   __restrict__ ridx_g,      // (B,N)
    const float* __restrict__ wk, const float* __restrict__ bk,
    const float* __restrict__ aw, const float* __restrict__ abias)
{
    __shared__ float xs[16][256];          // 16 KB
    __shared__ int   ridx[16];
    const int tid = threadIdx.x;
    const int blk = blockIdx.x;

    if (blk < 256) {
        // ---- qdg part: 8 rows ----
        const int row0 = blk * 8;
        for (int r = 0; r < 8; r++) xs[r][tid] = hlast[(size_t)(row0 + r) * Hdim + tid];
        __syncthreads();

        float aq[8], ad[8], ag[8];
        #pragma unroll
        for (int r = 0; r < 8; r++) { aq[r] = 0.f; ad[r] = 0.f; ag[r] = 0.f; }

        const float4* Q4 = (const float4*)(wq + (size_t)tid * Hdim);
        const float4* D4 = (const float4*)(wd + (size_t)tid * Hdim);
        const float4* G4 = (const float4*)(wg + (size_t)tid * Hdim);
        for (int j4 = 0; j4 < 64; j4++) {
            float4 q4 = Q4[j4], d4 = D4[j4], g4 = G4[j4];
            #pragma unroll
            for (int r = 0; r < 8; r++) {
                float4 x = *(const float4*)&xs[r][j4 * 4];
                aq[r] += x.x * q4.x + x.y * q4.y + x.z * q4.z + x.w * q4.w;
                ad[r] += x.x * d4.x + x.y * d4.y + x.z * d4.z + x.w * d4.w;
                ag[r] += x.x * g4.x + x.y * g4.y + x.z * g4.z + x.w * g4.w;
            }
        }
        float bqv = bq[tid], bdv = bd[tid], bgv = bg[tid];
        for (int r = 0; r < 8; r++) {
            size_t o = (size_t)(row0 + r) * Hdim + tid;
            g_q[o]   = (aq[r] + bqv) * 0.0625f;          // * H^-0.5
            g_ewd[o] = __expf(-(ad[r] + bdv));           // factorized sigmoid
            g_ug[o]  = ag[r] + bgv;
        }
    } else if (blk < 512) {
        // ---- k part: 16 rows ----
        const int row0 = (blk - 256) * 16;
        if (tid < 16) ridx[tid] = ridx_g[row0 + tid];
        __syncthreads();
        for (int i = tid; i < 16 * 256; i += 256) {
            int r = i >> 8, j = i & 255;
            xs[r][j] = rel_table[(size_t)ridx[r] * Hdim + j];
        }
        __syncthreads();

        float acc[16];
        #pragma unroll
        for (int r = 0; r < 16; r++) acc[r] = 0.f;
        const float4* W4 = (const float4*)(wk + (size_t)tid * Hdim);
        for (int j4 = 0; j4 < 64; j4++) {
            float4 w = W4[j4];
            #pragma unroll
            for (int r = 0; r < 16; r++) {
                float4 x = *(const float4*)&xs[r][j4 * 4];
                acc[r] += x.x * w.x + x.y * w.y + x.z * w.z + x.w * w.w;
            }
        }
        float bkv = bk[tid];
        for (int r = 0; r < 16; r++)
            g_k[(size_t)(row0 + r) * Hdim + tid] = acc[r] + bkv;
    } else {
        // ---- aerfa: warp b handles batch b ----
        const int b = tid >> 5, lane = tid & 31;
        const float* x = hlast + ((size_t)b * Tdim + (Tdim - 1)) * Hdim;
        float s = 0.f;
        #pragma unroll
        for (int j = lane; j < Hdim; j += 32) s += x[j] * aw[j];
        s = warp_sum(s);
        if (lane == 0) g_a[b] = __fdividef(1.0f, 1.0f + __expf(-(s + abias[0])));
    }
}

// ---------------------------------------------------------------------------
// Kernel 3: scores = q.k^T (masked) then softmax over n -> pasi
// ---------------------------------------------------------------------------
__global__ __launch_bounds__(256) void score_kernel(const int* __restrict__ tri_mask)
{
    __shared__ float qs[8][256];
    __shared__ float sc[8][512];
    const int tid  = threadIdx.x;
    const int row0 = blockIdx.x * 8;       // flattened b*T + t
    const int b    = row0 / Tdim;

    for (int r = 0; r < 8; r++) qs[r][tid] = g_q[(size_t)(row0 + r) * Hdim + tid];
    __syncthreads();

    float a0[8], a1[8];
    #pragma unroll
    for (int r = 0; r < 8; r++) { a0[r] = 0.f; a1[r] = 0.f; }

    const float* kb = g_k + (size_t)b * Ndim * Hdim;
    const float4* K0 = (const float4*)(kb + (size_t)tid * Hdim);
    const float4* K1 = (const float4*)(kb + (size_t)(tid + 256) * Hdim);
    for (int j4 = 0; j4 < 64; j4++) {
        float4 k0 = K0[j4], k1 = K1[j4];
        #pragma unroll
        for (int r = 0; r < 8; r++) {
            float4 q = *(const float4*)&qs[r][j4 * 4];
            a0[r] += q.x * k0.x + q.y * k0.y + q.z * k0.z + q.w * k0.w;
            a1[r] += q.x * k1.x + q.y * k1.y + q.z * k1.z + q.w * k1.w;
        }
    }
    int m0 = tri_mask[b * Ndim + tid];
    int m1 = tri_mask[b * Ndim + tid + 256];
    for (int r = 0; r < 8; r++) {
        sc[r][tid]       = (m0 == 1) ? a0[r] : -1.0e9f;
        sc[r][tid + 256] = (m1 == 1) ? a1[r] : -1.0e9f;
    }
    __syncthreads();

    const int wid = tid >> 5, lane = tid & 31;
    float* row = sc[wid];
    float mx = -3.4e38f;
    #pragma unroll
    for (int i = lane; i < 512; i += 32) mx = fmaxf(mx, row[i]);
    mx = warp_max(mx);
    float sum = 0.f;
    #pragma unroll
    for (int i = lane; i < 512; i += 32) {
        float e = __expf(row[i] - mx);
        row[i] = e;
        sum += e;
    }
    sum = warp_sum(sum);
    float inv = __fdividef(1.0f, sum);
    float* pout = g_pasi + (size_t)(row0 + wid) * Ndim;
    #pragma unroll
    for (int i = lane; i < 512; i += 32) pout[i] = row[i] * inv;
}

// ---------------------------------------------------------------------------
// Kernel 4: the sequential scan. One warp per (b,n), u in registers.
// grid: (N/8, B) x 256 thr.  h = lane*8 + j.
// sigmoid(wd+wu) = 1 / (1 + exp(-wd)*exp(-wu))  -> 1 EX2 + 8 RCP per step.
// Double-buffered SMEM reduction: ONE barrier per t.
// ---------------------------------------------------------------------------
__global__ __launch_bounds__(256) void scan_kernel(
    const float* __restrict__ wu_w,        // (1,H)
    const float* __restrict__ wu_b,        // (1)
    float* __restrict__ out)               // (B,T,H)
{
    __shared__ float sacc[2][2048];        // 16 KB
    const int b    = blockIdx.y;
    const int wid  = threadIdx.x >> 5;
    const int lane = threadIdx.x & 31;
    const int n    = blockIdx.x * 8 + wid;
    const int tid  = threadIdx.x;

    float u[8], wv[8];
    {
        const float4* u0p = (const float4*)(g_u0 + ((size_t)b * Ndim + n) * Hdim + lane * 8);
        float4 ua = u0p[0], ub = u0p[1];
        u[0]=ua.x; u[1]=ua.y; u[2]=ua.z; u[3]=ua.w;
        u[4]=ub.x; u[5]=ub.y; u[6]=ub.z; u[7]=ub.w;
        const float4* wp = (const float4*)(wu_w + lane * 8);
        float4 wa = wp[0], wb = wp[1];
        wv[0]=wa.x; wv[1]=wa.y; wv[2]=wa.z; wv[3]=wa.w;
        wv[4]=wb.x; wv[5]=wb.y; wv[6]=wb.z; wv[7]=wb.w;
    }
    const float wub = wu_b[0];
    const float ab  = g_a[b];
    const float* pas = g_pasi + (size_t)b * Tdim * Ndim + n;
    const float* edb = g_ewd + (size_t)b * Tdim * Hdim + lane * 8;
    const float* ugb = g_ug  + (size_t)b * Tdim * Hdim + lane * 8;
    float* outb = out + (size_t)b * Tdim * Hdim;

    // preload t = 0
    float4 e0 = *(const float4*)(edb + 0);
    float4 e1 = *(const float4*)(edb + 4);
    float4 g0 = *(const float4*)(ugb + 0);
    float4 g1 = *(const float4*)(ugb + 4);
    float  pv = pas[0];

    #pragma unroll 2
    for (int t = 0; t < Tdim; t++) {
        // wu = u . wu_w + wu_b  (uses PRE-update u)
        float s = 0.f;
        #pragma unroll
        for (int j = 0; j < 8; j++) s += u[j] * wv[j];
        s = warp_sum(s);
        float En = __expf(-(s + wub));       // exp(-wu)

        float ew[8] = {e0.x,e0.y,e0.z,e0.w,e1.x,e1.y,e1.z,e1.w};
        float ug[8] = {g0.x,g0.y,g0.z,g0.w,g1.x,g1.y,g1.z,g1.w};
        float p = pv;

        // prefetch t+1 (overlaps MUFU + barrier below)
        if (t + 1 < Tdim) {
            const float* ed = edb + (size_t)(t + 1) * Hdim;
            const float* ugp = ugb + (size_t)(t + 1) * Hdim;
            e0 = *(const float4*)(ed);
            e1 = *(const float4*)(ed + 4);
            g0 = *(const float4*)(ugp);
            g1 = *(const float4*)(ugp + 4);
            pv = pas[(size_t)(t + 1) * Ndim];
        }

        float c[8];
        #pragma unroll
        for (int j = 0; j < 8; j++) {
            float den  = fmaf(ew[j], En, 1.0f);
            float beta = __fdividef(ab, den);          // a * sigmoid(wd+wu)
            u[j] = fmaf(beta, ug[j] - u[j], u[j]);     // u*(1-b) + ug*b
            c[j] = u[j] * p;
        }
        float* dst = &sacc[t & 1][wid * 256 + lane * 8];
        ((float4*)dst)[0] = make_float4(c[0], c[1], c[2], c[3]);
        ((float4*)dst)[1] = make_float4(c[4], c[5], c[6], c[7]);

        __syncthreads();
        {
            const float* buf = sacc[t & 1];
            float sum = 0.f;
            #pragma unroll
            for (int w = 0; w < 8; w++) sum += buf[w * 256 + tid];
            atomicAdd(&outb[(size_t)t * Hdim + tid], sum);
        }
        // no second barrier: next iteration writes the other buffer, and the
        // next iteration's barrier fences the t+2 overwrite of this buffer.
    }
}

// ---------------------------------------------------------------------------
extern "C" void kernel_launch(void* const* d_in, const int* in_sizes, int n_in,
                              void* d_out, int out_size)
{
    const float* hidden   = (const float*)d_in[0];
    const float* SE       = (const float*)d_in[1];
    const float* rel_tab  = (const float*)d_in[2];
    const float* sq_w     = (const float*)d_in[3];
    const float* sq_b     = (const float*)d_in[4];
    const float* ae_w     = (const float*)d_in[5];
    const float* ae_b     = (const float*)d_in[6];
    const float* wq_w     = (const float*)d_in[7];
    const float* wq_b     = (const float*)d_in[8];
    const float* wk_w     = (const float*)d_in[9];
    const float* wk_b     = (const float*)d_in[10];
    const float* wd_w     = (const float*)d_in[11];
    const float* wd_b     = (const float*)d_in[12];
    const float* wu_w     = (const float*)d_in[13];
    const float* wu_b     = (const float*)d_in[14];
    const float* wg_w     = (const float*)d_in[15];
    const float* wg_b     = (const float*)d_in[16];
    const int*   heads    = (const int*)d_in[17];
    const int*   tails    = (const int*)d_in[18];
    const int*   tri_mask = (const int*)d_in[19];
    const int*   rel_idx  = (const int*)d_in[20];
    float* out = (float*)d_out;

    const float* h_last = hidden + (size_t)(Ldim - 1) * Bdim * Tdim * Hdim;

    cudaMemsetAsync(out, 0, (size_t)out_size * sizeof(float), 0);

    u0_kernel<<<(Bdim * Ndim) / 16, 256>>>(SE, heads, tails, sq_w, sq_b, tri_mask);
    mid_kernel<<<513, 256>>>(h_last, wq_w, wq_b, wd_w, wd_b, wg_w, wg_b,
                             rel_tab, rel_idx, wk_w, wk_b, ae_w, ae_b);
    score_kernel<<<(Bdim * Tdim) / 8, 256>>>(tri_mask);
    scan_kernel<<<dim3(Ndim / 8, Bdim), 256>>>(wu_w, wu_b, out);
}

// round 5
// speedup vs baseline: 1.1545x; 1.1158x over previous
#include <cuda_runtime.h>
#include <cuda_bf16.h>
#include <cstdint>

// Problem dims
#define Ldim 2
#define Bdim 8
#define Tdim 256
#define Ndim 512
#define Kdim 16
#define Mdim 10000
#define Hdim 256
#define Rdim 500

// Scratch (device globals -- no allocation allowed)
__device__ float g_u0[Bdim * Ndim * Hdim];       // 4 MB
__device__ float g_q[Bdim * Tdim * Hdim];        // 2 MB
__device__ float g_k[Bdim * Ndim * Hdim];        // 4 MB
__device__ float g_ewd[Bdim * Tdim * Hdim];      // 2 MB : exp(-(h@wd.T+bd))
__device__ float g_ug[Bdim * Tdim * Hdim];       // 2 MB
__device__ float g_pasi[Bdim * Tdim * Ndim];     // 4 MB
__device__ float g_a[Bdim];

__device__ __forceinline__ float warp_sum(float v) {
    #pragma unroll
    for (int o = 16; o > 0; o >>= 1) v += __shfl_xor_sync(0xffffffffu, v, o);
    return v;
}
__device__ __forceinline__ float warp_max(float v) {
    #pragma unroll
    for (int o = 16; o > 0; o >>= 1) v = fmaxf(v, __shfl_xor_sync(0xffffffffu, v, o));
    return v;
}

// ---------------------------------------------------------------------------
// Kernel 1: u0 = concat([sum_k SE[heads], sum_k SE[tails]]) @ squeeze_w.T + b,
//           zeroed where tri_mask != 1.  grid: 256 blocks x 256 thr (16 rows).
// ---------------------------------------------------------------------------
__global__ __launch_bounds__(256) void u0_kernel(
    const float* __restrict__ SE,          // (B,M,H)
    const int*   __restrict__ heads,       // (B,N,K)
    const int*   __restrict__ tails,       // (B,N,K)
    const float* __restrict__ squeeze_w,   // (H,2H)
    const float* __restrict__ squeeze_b,   // (H)
    const int*   __restrict__ tri_mask)    // (B,N)
{
    __shared__ float cat_s[16][512];       // 32 KB
    __shared__ int   sidx[16][32];         // heads 0..15, tails 16..31

    const int tid  = threadIdx.x;
    const int row0 = blockIdx.x * 16;      // flattened b*N+n
    const int b    = row0 / Ndim;

    for (int i = tid; i < 16 * 32; i += 256) {
        int r = i >> 5, j = i & 31;
        int gr = row0 + r;
        sidx[r][j] = (j < 16) ? heads[gr * Kdim + j] : tails[gr * Kdim + (j - 16)];
    }
    __syncthreads();

    const float* SEb = SE + (size_t)b * Mdim * Hdim;
    for (int r = 0; r < 16; r++) {
        float he = 0.f, te = 0.f;
        #pragma unroll
        for (int k = 0; k < 16; k++) {
            he += SEb[(size_t)sidx[r][k] * Hdim + tid];
            te += SEb[(size_t)sidx[r][16 + k] * Hdim + tid];
        }
        cat_s[r][tid]       = he;
        cat_s[r][256 + tid] = te;
    }
    __syncthreads();

    float acc[16];
    #pragma unroll
    for (int r = 0; r < 16; r++) acc[r] = 0.f;

    const float4* W4 = (const float4*)(squeeze_w + (size_t)tid * 512);
    for (int j4 = 0; j4 < 128; j4++) {
        float4 w = W4[j4];
        #pragma unroll
        for (int r = 0; r < 16; r++) {
            float4 c = *(const float4*)&cat_s[r][j4 * 4];
            acc[r] += c.x * w.x + c.y * w.y + c.z * w.z + c.w * w.w;
        }
    }
    float bias = squeeze_b[tid];
    for (int r = 0; r < 16; r++) {
        int gr = row0 + r;
        float v = (tri_mask[gr] == 1) ? (acc[r] + bias) : 0.f;
        g_u0[(size_t)gr * Hdim + tid] = v;
    }
}

// ---------------------------------------------------------------------------
// Kernel 2 (fused): blocks [0,256)  : q, ewd=exp(-wd), ug from h_last
//                   blocks [256,512): k = rel_table[ridx] @ wk.T + bk
//                   block  512      : aerfa per batch
// ---------------------------------------------------------------------------
__global__ __launch_bounds__(256) void mid_kernel(
    const float* __restrict__ hlast,       // (B*T, H)
    const float* __restrict__ wq, const float* __restrict__ bq,
    const float* __restrict__ wd, const float* __restrict__ bd,
    const float* __restrict__ wg, const float* __restrict__ bg,
    const float* __restrict__ rel_table,   // (R,H)
    const int*   __restrict__ ridx_g,      // (B,N)
    const float* __restrict__ wk, const float* __restrict__ bk,
    const float* __restrict__ aw, const float* __restrict__ abias)
{
    __shared__ float xs[16][256];          // 16 KB
    __shared__ int   ridx[16];
    const int tid = threadIdx.x;
    const int blk = blockIdx.x;

    if (blk < 256) {
        // ---- qdg part: 8 rows ----
        const int row0 = blk * 8;
        for (int r = 0; r < 8; r++) xs[r][tid] = hlast[(size_t)(row0 + r) * Hdim + tid];
        __syncthreads();

        float aq[8], ad[8], ag[8];
        #pragma unroll
        for (int r = 0; r < 8; r++) { aq[r] = 0.f; ad[r] = 0.f; ag[r] = 0.f; }

        const float4* Q4 = (const float4*)(wq + (size_t)tid * Hdim);
        const float4* D4 = (const float4*)(wd + (size_t)tid * Hdim);
        const float4* G4 = (const float4*)(wg + (size_t)tid * Hdim);
        for (int j4 = 0; j4 < 64; j4++) {
            float4 q4 = Q4[j4], d4 = D4[j4], g4 = G4[j4];
            #pragma unroll
            for (int r = 0; r < 8; r++) {
                float4 x = *(const float4*)&xs[r][j4 * 4];
                aq[r] += x.x * q4.x + x.y * q4.y + x.z * q4.z + x.w * q4.w;
                ad[r] += x.x * d4.x + x.y * d4.y + x.z * d4.z + x.w * d4.w;
                ag[r] += x.x * g4.x + x.y * g4.y + x.z * g4.z + x.w * g4.w;
            }
        }
        float bqv = bq[tid], bdv = bd[tid], bgv = bg[tid];
        for (int r = 0; r < 8; r++) {
            size_t o = (size_t)(row0 + r) * Hdim + tid;
            g_q[o]   = (aq[r] + bqv) * 0.0625f;          // * H^-0.5
            g_ewd[o] = __expf(-(ad[r] + bdv));           // factorized sigmoid
            g_ug[o]  = ag[r] + bgv;
        }
    } else if (blk < 512) {
        // ---- k part: 16 rows ----
        const int row0 = (blk - 256) * 16;
        if (tid < 16) ridx[tid] = ridx_g[row0 + tid];
        __syncthreads();
        for (int i = tid; i < 16 * 256; i += 256) {
            int r = i >> 8, j = i & 255;
            xs[r][j] = rel_table[(size_t)ridx[r] * Hdim + j];
        }
        __syncthreads();

        float acc[16];
        #pragma unroll
        for (int r = 0; r < 16; r++) acc[r] = 0.f;
        const float4* W4 = (const float4*)(wk + (size_t)tid * Hdim);
        for (int j4 = 0; j4 < 64; j4++) {
            float4 w = W4[j4];
            #pragma unroll
            for (int r = 0; r < 16; r++) {
                float4 x = *(const float4*)&xs[r][j4 * 4];
                acc[r] += x.x * w.x + x.y * w.y + x.z * w.z + x.w * w.w;
            }
        }
        float bkv = bk[tid];
        for (int r = 0; r < 16; r++)
            g_k[(size_t)(row0 + r) * Hdim + tid] = acc[r] + bkv;
    } else {
        // ---- aerfa: warp b handles batch b ----
        const int b = tid >> 5, lane = tid & 31;
        const float* x = hlast + ((size_t)b * Tdim + (Tdim - 1)) * Hdim;
        float s = 0.f;
        #pragma unroll
        for (int j = lane; j < Hdim; j += 32) s += x[j] * aw[j];
        s = warp_sum(s);
        if (lane == 0) g_a[b] = __fdividef(1.0f, 1.0f + __expf(-(s + abias[0])));
    }
}

// ---------------------------------------------------------------------------
// Kernel 3: scores = q.k^T (masked) then softmax over n -> pasi
// ---------------------------------------------------------------------------
__global__ __launch_bounds__(256) void score_kernel(const int* __restrict__ tri_mask)
{
    __shared__ float qs[8][256];
    __shared__ float sc[8][512];
    const int tid  = threadIdx.x;
    const int row0 = blockIdx.x * 8;       // flattened b*T + t
    const int b    = row0 / Tdim;

    for (int r = 0; r < 8; r++) qs[r][tid] = g_q[(size_t)(row0 + r) * Hdim + tid];
    __syncthreads();

    float a0[8], a1[8];
    #pragma unroll
    for (int r = 0; r < 8; r++) { a0[r] = 0.f; a1[r] = 0.f; }

    const float* kb = g_k + (size_t)b * Ndim * Hdim;
    const float4* K0 = (const float4*)(kb + (size_t)tid * Hdim);
    const float4* K1 = (const float4*)(kb + (size_t)(tid + 256) * Hdim);
    for (int j4 = 0; j4 < 64; j4++) {
        float4 k0 = K0[j4], k1 = K1[j4];
        #pragma unroll
        for (int r = 0; r < 8; r++) {
            float4 q = *(const float4*)&qs[r][j4 * 4];
            a0[r] += q.x * k0.x + q.y * k0.y + q.z * k0.z + q.w * k0.w;
            a1[r] += q.x * k1.x + q.y * k1.y + q.z * k1.z + q.w * k1.w;
        }
    }
    int m0 = tri_mask[b * Ndim + tid];
    int m1 = tri_mask[b * Ndim + tid + 256];
    for (int r = 0; r < 8; r++) {
        sc[r][tid]       = (m0 == 1) ? a0[r] : -1.0e9f;
        sc[r][tid + 256] = (m1 == 1) ? a1[r] : -1.0e9f;
    }
    __syncthreads();

    const int wid = tid >> 5, lane = tid & 31;
    float* row = sc[wid];
    float mx = -3.4e38f;
    #pragma unroll
    for (int i = lane; i < 512; i += 32) mx = fmaxf(mx, row[i]);
    mx = warp_max(mx);
    float sum = 0.f;
    #pragma unroll
    for (int i = lane; i < 512; i += 32) {
        float e = __expf(row[i] - mx);
        row[i] = e;
        sum += e;
    }
    sum = warp_sum(sum);
    float inv = __fdividef(1.0f, sum);
    float* pout = g_pasi + (size_t)(row0 + wid) * Ndim;
    #pragma unroll
    for (int i = lane; i < 512; i += 32) pout[i] = row[i] * inv;
}

// ---------------------------------------------------------------------------
// Kernel 4: the sequential scan. One warp per (b,n), u in registers.
// grid: (N/8, B) x 256 thr.
// NEW h-mapping: thread (lane) owns h = j*64 + 2*lane + {0,1}, j=0..3.
// Every global/shared access is fully coalesced (float2, 8B lane stride),
// full 32B-sector utilization, zero SMEM bank conflicts.
// sigmoid(wd+wu) = 1/(1 + exp(-wd)*exp(-wu)) -> 1 EX2 + 8 RCP per step.
// Double-buffered SMEM reduction: ONE barrier per t.
// ---------------------------------------------------------------------------
__global__ __launch_bounds__(256) void scan_kernel(
    const float* __restrict__ wu_w,        // (1,H)
    const float* __restrict__ wu_b,        // (1)
    float* __restrict__ out)               // (B,T,H)
{
    __shared__ float sacc[2][2048];        // 16 KB
    const int b    = blockIdx.y;
    const int wid  = threadIdx.x >> 5;
    const int lane = threadIdx.x & 31;
    const int n    = blockIdx.x * 8 + wid;
    const int tid  = threadIdx.x;
    const int h0   = lane * 2;             // offset within each 64-float chunk

    float u[8], wv[8];
    {
        const float* ubase = g_u0 + ((size_t)b * Ndim + n) * Hdim;
        #pragma unroll
        for (int j = 0; j < 4; j++) {
            float2 uu = *(const float2*)(ubase + j * 64 + h0);
            u[2*j] = uu.x; u[2*j+1] = uu.y;
            float2 ww = *(const float2*)(wu_w + j * 64 + h0);
            wv[2*j] = ww.x; wv[2*j+1] = ww.y;
        }
    }
    const float wub = wu_b[0];
    const float ab  = g_a[b];
    const float* pas = g_pasi + (size_t)b * Tdim * Ndim + n;
    const float* edb = g_ewd + (size_t)b * Tdim * Hdim + h0;
    const float* ugb = g_ug  + (size_t)b * Tdim * Hdim + h0;
    float* outb = out + (size_t)b * Tdim * Hdim;

    // preload t = 0
    float2 e2[4], g2[4];
    #pragma unroll
    for (int j = 0; j < 4; j++) {
        e2[j] = *(const float2*)(edb + j * 64);
        g2[j] = *(const float2*)(ugb + j * 64);
    }
    float pv = pas[0];

    #pragma unroll 2
    for (int t = 0; t < Tdim; t++) {
        // wu = u . wu_w + wu_b  (uses PRE-update u)
        float s = 0.f;
        #pragma unroll
        for (int j = 0; j < 8; j++) s += u[j] * wv[j];
        s = warp_sum(s);
        float En = __expf(-(s + wub));       // exp(-wu)

        float ew[8] = {e2[0].x,e2[0].y,e2[1].x,e2[1].y,e2[2].x,e2[2].y,e2[3].x,e2[3].y};
        float ug[8] = {g2[0].x,g2[0].y,g2[1].x,g2[1].y,g2[2].x,g2[2].y,g2[3].x,g2[3].y};
        float p = pv;

        // prefetch t+1 (overlaps MUFU + barrier below)
        if (t + 1 < Tdim) {
            const float* ed = edb + (size_t)(t + 1) * Hdim;
            const float* ugp = ugb + (size_t)(t + 1) * Hdim;
            #pragma unroll
            for (int j = 0; j < 4; j++) {
                e2[j] = *(const float2*)(ed + j * 64);
                g2[j] = *(const float2*)(ugp + j * 64);
            }
            pv = pas[(size_t)(t + 1) * Ndim];
        }

        float c[8];
        #pragma unroll
        for (int j = 0; j < 8; j++) {
            float den  = fmaf(ew[j], En, 1.0f);
            float beta = __fdividef(ab, den);          // a * sigmoid(wd+wu)
            u[j] = fmaf(beta, ug[j] - u[j], u[j]);     // u*(1-b) + ug*b
            c[j] = u[j] * p;
        }
        // value for h goes to sacc[buf][wid*256 + h]; h = j*64 + h0 (+1)
        float* dst = &sacc[t & 1][wid * 256 + h0];
        #pragma unroll
        for (int j = 0; j < 4; j++)
            *(float2*)(dst + j * 64) = make_float2(c[2*j], c[2*j+1]);

        __syncthreads();
        {
            const float* buf = sacc[t & 1];
            float sum = 0.f;
            #pragma unroll
            for (int w = 0; w < 8; w++) sum += buf[w * 256 + tid];
            atomicAdd(&outb[(size_t)t * Hdim + tid], sum);
        }
        // no second barrier: next iteration writes the other buffer, and the
        // next iteration's barrier fences the t+2 overwrite of this buffer.
    }
}

// ---------------------------------------------------------------------------
extern "C" void kernel_launch(void* const* d_in, const int* in_sizes, int n_in,
                              void* d_out, int out_size)
{
    const float* hidden   = (const float*)d_in[0];
    const float* SE       = (const float*)d_in[1];
    const float* rel_tab  = (const float*)d_in[2];
    const float* sq_w     = (const float*)d_in[3];
    const float* sq_b     = (const float*)d_in[4];
    const float* ae_w     = (const float*)d_in[5];
    const float* ae_b     = (const float*)d_in[6];
    const float* wq_w     = (const float*)d_in[7];
    const float* wq_b     = (const float*)d_in[8];
    const float* wk_w     = (const float*)d_in[9];
    const float* wk_b     = (const float*)d_in[10];
    const float* wd_w     = (const float*)d_in[11];
    const float* wd_b     = (const float*)d_in[12];
    const float* wu_w     = (const float*)d_in[13];
    const float* wu_b     = (const float*)d_in[14];
    const float* wg_w     = (const float*)d_in[15];
    const float* wg_b     = (const float*)d_in[16];
    const int*   heads    = (const int*)d_in[17];
    const int*   tails    = (const int*)d_in[18];
    const int*   tri_mask = (const int*)d_in[19];
    const int*   rel_idx  = (const int*)d_in[20];
    float* out = (float*)d_out;

    const float* h_last = hidden + (size_t)(Ldim - 1) * Bdim * Tdim * Hdim;

    cudaMemsetAsync(out, 0, (size_t)out_size * sizeof(float), 0);

    u0_kernel<<<(Bdim * Ndim) / 16, 256>>>(SE, heads, tails, sq_w, sq_b, tri_mask);
    mid_kernel<<<513, 256>>>(h_last, wq_w, wq_b, wd_w, wd_b, wg_w, wg_b,
                             rel_tab, rel_idx, wk_w, wk_b, ae_w, ae_b);
    score_kernel<<<(Bdim * Tdim) / 8, 256>>>(tri_mask);
    scan_kernel<<<dim3(Ndim / 8, Bdim), 256>>>(wu_w, wu_b, out);
}